// round 11
// baseline (speedup 1.0000x reference)
#include <cuda_runtime.h>
#include <cuda_fp16.h>

#define NN 100000
#define HH 64
#define GG 512
#define ELLW 64           // fixed ELL width; P(deg>64) ~ 1e-30 for Poisson(12)

// -------- scratch (device globals; zero-initialized at module load) --------
// INVARIANT: g_ideg, g_pool, g_cnt are all-zero on entry to every kernel_launch
// call. k_final restores this invariant at the end of each call.
__device__ int    g_ideg[NN];
__device__ int    g_ell[NN * ELLW];   // ELL: src indices per dst node (rows 256B-aligned)
__device__ float  g_dinv[NN];
__device__ __half g_th[NN * HH];      // pre-scaled transformed features (fp16)
__device__ float  g_f[NN * HH];       // layer-1 output (fp32)
__device__ float  g_pool[GG * HH];
__device__ float  g_cnt[GG];

// One pass: ELL fill (replaces hist+scan+fill) + warp-aggregated graph counts
__global__ void k_fill_ell(const int* __restrict__ src, const int* __restrict__ dst, int E,
                           const int* __restrict__ batch, int n) {
    int i = blockIdx.x * blockDim.x + threadIdx.x;
    if (i < E) {
        int d = dst[i];
        int slot = atomicAdd(&g_ideg[d], 1);
        if (slot < ELLW) g_ell[d * ELLW + slot] = src[i];
    }
    if (i < n) {
        // batch sorted -> ~1-2 atomics per warp
        int b = batch[i];
        unsigned active = __activemask();
        unsigned peers = __match_any_sync(active, b);
        int leader = __ffs(peers) - 1;
        int cnt = __popc(peers);
        if ((threadIdx.x & 31) == leader) atomicAdd(&g_cnt[b], (float)cnt);
    }
}

__global__ void k_dinv(int n) {
    int i = blockIdx.x * blockDim.x + threadIdx.x;
    if (i < n) g_dinv[i] = rsqrtf((float)g_ideg[i] + 1.0f);
}

// t1' = dinv * (x @ W1), fp16 store
__global__ void k_xform1(const float* __restrict__ x, const float* __restrict__ W1, int n) {
    int i = blockIdx.x * blockDim.x + threadIdx.x;
    if (i >= n * HH) return;
    int node = i >> 6;
    int j = i & 63;
    float v = g_dinv[node] * (x[2 * node] * W1[j] + x[2 * node + 1] * W1[HH + j]);
    g_th[i] = __float2half(v);
}

// warp-per-node aggregation core: uniform int4 index loads (no shfl),
// fp16 gathers, fp32 accum, 4 independent accumulators.
__device__ __forceinline__ float2 agg_node(const __half2* __restrict__ t2, int w, int lane) {
    int len = g_ideg[w];
    if (len > ELLW) len = ELLW;
    const int* row = &g_ell[w * ELLW];
    float2 a0 = __half22float2(t2[w * 32 + lane]);   // self
    float2 a1 = make_float2(0.f, 0.f);
    float2 a2 = make_float2(0.f, 0.f);
    float2 a3 = make_float2(0.f, 0.f);
    int k = 0;
    for (; k + 4 <= len; k += 4) {
        int4 q = *reinterpret_cast<const int4*>(row + k);   // uniform across warp
        float2 v0 = __half22float2(t2[q.x * 32 + lane]);
        float2 v1 = __half22float2(t2[q.y * 32 + lane]);
        float2 v2 = __half22float2(t2[q.z * 32 + lane]);
        float2 v3 = __half22float2(t2[q.w * 32 + lane]);
        a0.x += v0.x; a0.y += v0.y;
        a1.x += v1.x; a1.y += v1.y;
        a2.x += v2.x; a2.y += v2.y;
        a3.x += v3.x; a3.y += v3.y;
    }
    for (; k < len; k++) {
        int s = row[k];
        float2 v = __half22float2(t2[s * 32 + lane]);
        a0.x += v.x; a0.y += v.y;
    }
    a0.x += (a1.x + a2.x) + a3.x;
    a0.y += (a1.y + a2.y) + a3.y;
    return a0;
}

__global__ void k_agg1(const float* __restrict__ b1, int n) {
    const __half2* t2 = reinterpret_cast<const __half2*>(g_th);
    int w = (blockIdx.x * blockDim.x + threadIdx.x) >> 5;
    int lane = threadIdx.x & 31;
    if (w >= n) return;
    float2 acc = agg_node(t2, w, lane);
    float dv = g_dinv[w];
    float2 bb = *reinterpret_cast<const float2*>(&b1[lane * 2]);
    float2 o;
    o.x = fmaxf(fmaf(dv, acc.x, bb.x), 0.0f);
    o.y = fmaxf(fmaf(dv, acc.y, bb.y), 0.0f);
    *reinterpret_cast<float2*>(&g_f[w * HH + lane * 2]) = o;
}

// t2' = dinv * (f1 @ W2); 16 nodes per 256-thread block
__global__ void k_xform2(const float* __restrict__ W2, int n) {
    __shared__ float sW[HH * HH];
    __shared__ float sRow[16][HH + 4];
    int tid = threadIdx.x;
    int nl = tid >> 4;
    int q  = tid & 15;
    int j4 = q * 4;
    int node = blockIdx.x * 16 + nl;

    for (int i = tid; i < HH * HH; i += 256) sW[i] = W2[i];
    if (node < n) {
        float4 r = *reinterpret_cast<const float4*>(&g_f[node * HH + j4]);
        sRow[nl][j4 + 0] = r.x; sRow[nl][j4 + 1] = r.y;
        sRow[nl][j4 + 2] = r.z; sRow[nl][j4 + 3] = r.w;
    }
    __syncthreads();

    if (node >= n) return;
    float a0 = 0.f, a1 = 0.f, a2 = 0.f, a3 = 0.f;
    #pragma unroll
    for (int k = 0; k < HH; k++) {
        float r = sRow[nl][k];
        float4 wv = *reinterpret_cast<const float4*>(&sW[k * HH + j4]);
        a0 = fmaf(r, wv.x, a0);
        a1 = fmaf(r, wv.y, a1);
        a2 = fmaf(r, wv.z, a2);
        a3 = fmaf(r, wv.w, a3);
    }
    float dv = g_dinv[node];
    __half2* out = reinterpret_cast<__half2*>(&g_th[node * HH + j4]);
    out[0] = __floats2half2_rn(dv * a0, dv * a1);
    out[1] = __floats2half2_rn(dv * a2, dv * a3);
}

// warp-per-node layer-2 agg fused with pooling
__global__ void k_agg2pool(const float* __restrict__ b2, const int* __restrict__ batch, int n) {
    const __half2* t2 = reinterpret_cast<const __half2*>(g_th);
    int w = (blockIdx.x * blockDim.x + threadIdx.x) >> 5;
    int lane = threadIdx.x & 31;
    if (w >= n) return;
    float2 acc = agg_node(t2, w, lane);
    float dv = g_dinv[w];
    float2 bb = *reinterpret_cast<const float2*>(&b2[lane * 2]);
    float vx = fmaxf(fmaf(dv, acc.x, bb.x), 0.0f);
    float vy = fmaxf(fmaf(dv, acc.y, bb.y), 0.0f);
    int b = batch[w];
    atomicAdd(&g_pool[b * HH + lane * 2 + 0], vx);
    atomicAdd(&g_pool[b * HH + lane * 2 + 1], vy);
}

// Head + restore zero-invariant for next call
__global__ void k_final(const float* __restrict__ Wf1, const float* __restrict__ bf1,
                        const float* __restrict__ Wf2, const float* __restrict__ bf2,
                        float* __restrict__ out) {
    __shared__ float sg[HH];
    __shared__ float sa[HH];
    int b = blockIdx.x;
    int j = threadIdx.x;

    float c = fmaxf(g_cnt[b], 1.0f);
    sg[j] = g_pool[b * HH + j] / c;
    __syncthreads();

    float acc = bf1[j];
    #pragma unroll
    for (int k = 0; k < HH; k++) acc += sg[k] * Wf1[k * HH + j];
    sa[j] = fmaxf(acc, 0.0f);
    __syncthreads();

    if (j < 4) {
        float o = bf2[j];
        #pragma unroll
        for (int k = 0; k < HH; k++) o += sa[k] * Wf2[k * 4 + j];
        out[b * 4 + j] = o;
    }

    // ---- restore zero-invariant ----
    g_pool[b * HH + j] = 0.0f;
    if (j == 0) g_cnt[b] = 0.0f;
    for (int i = b * HH + j; i < NN; i += GG * HH) g_ideg[i] = 0;
}

extern "C" void kernel_launch(void* const* d_in, const int* in_sizes, int n_in,
                              void* d_out, int out_size) {
    const float* x          = (const float*)d_in[0];
    const int*   edge_index = (const int*)d_in[1];
    const int*   batch      = (const int*)d_in[2];
    int wb = n_in - 8;
    const float* W1  = (const float*)d_in[wb + 0];
    const float* b1  = (const float*)d_in[wb + 1];
    const float* W2  = (const float*)d_in[wb + 2];
    const float* b2  = (const float*)d_in[wb + 3];
    const float* Wf1 = (const float*)d_in[wb + 4];
    const float* bf1 = (const float*)d_in[wb + 5];
    const float* Wf2 = (const float*)d_in[wb + 6];
    const float* bf2 = (const float*)d_in[wb + 7];

    int N = in_sizes[0] / 2;   // 100000
    int E = in_sizes[1] / 2;   // 1200000
    const int* src = edge_index;
    const int* dst = edge_index + E;

    float* out = (float*)d_out;
    (void)out_size;

    const int T = 256;
    int gN  = (N + T - 1) / T;
    int gE  = (E + T - 1) / T;
    int gNH = (N * HH + T - 1) / T;
    int gW  = (N * 32 + T - 1) / T;      // warp-per-node

    k_fill_ell<<<gE, T>>>(src, dst, E, batch, N);   // 0
    k_dinv<<<gN, T>>>(N);                           // 1
    k_xform1<<<gNH, T>>>(x, W1, N);                 // 2
    k_agg1<<<gW, T>>>(b1, N);                       // 3  <- profiled (verify shfl removal)
    k_xform2<<<(N + 15) / 16, 256>>>(W2, N);        // 4
    k_agg2pool<<<gW, T>>>(b2, batch, N);            // 5
    k_final<<<GG, HH>>>(Wf1, bf1, Wf2, bf2, out);   // 6
}

// round 12
// speedup vs baseline: 1.1395x; 1.1395x over previous
#include <cuda_runtime.h>
#include <cuda_fp16.h>

#define NN 100000
#define HH 64
#define GG 512
#define ELLW 64           // fixed ELL width; P(deg>64) ~ 1e-30 for Poisson(12)

// -------- scratch (device globals; zero-initialized at module load) --------
// INVARIANT: g_ideg, g_pool, g_cnt are all-zero on entry to every kernel_launch
// call. k_final restores this invariant at the end of each call.
__device__ int    g_ideg[NN];
__device__ int    g_ell[NN * ELLW];   // ELL: src indices per dst node
__device__ float  g_dinv[NN];
__device__ __half g_th[NN * HH];      // pre-scaled transformed features (fp16)
__device__ float  g_f[NN * HH];       // layer-1 output (fp32)
__device__ float  g_pool[GG * HH];
__device__ float  g_cnt[GG];

// One pass: ELL fill (replaces hist+scan+fill) + warp-aggregated graph counts
__global__ void k_fill_ell(const int* __restrict__ src, const int* __restrict__ dst, int E,
                           const int* __restrict__ batch, int n) {
    int i = blockIdx.x * blockDim.x + threadIdx.x;
    if (i < E) {
        int d = dst[i];
        int slot = atomicAdd(&g_ideg[d], 1);
        if (slot < ELLW) g_ell[d * ELLW + slot] = src[i];
    }
    if (i < n) {
        // batch sorted -> ~1-2 atomics per warp
        int b = batch[i];
        unsigned active = __activemask();
        unsigned peers = __match_any_sync(active, b);
        int leader = __ffs(peers) - 1;
        int cnt = __popc(peers);
        if ((threadIdx.x & 31) == leader) atomicAdd(&g_cnt[b], (float)cnt);
    }
}

__global__ void k_dinv(int n) {
    int i = blockIdx.x * blockDim.x + threadIdx.x;
    if (i < n) g_dinv[i] = rsqrtf((float)g_ideg[i] + 1.0f);
}

// t1' = dinv * (x @ W1), fp16 store
__global__ void k_xform1(const float* __restrict__ x, const float* __restrict__ W1, int n) {
    int i = blockIdx.x * blockDim.x + threadIdx.x;
    if (i >= n * HH) return;
    int node = i >> 6;
    int j = i & 63;
    float v = g_dinv[node] * (x[2 * node] * W1[j] + x[2 * node + 1] * W1[HH + j]);
    g_th[i] = __float2half(v);
}

// warp-per-node aggregation core: coalesced index load + shfl broadcast (R10-proven),
// fp16 HADD2 accumulation in 4 independent accumulators, fp32 combine at the end.
__device__ __forceinline__ float2 agg_node(const __half2* __restrict__ t2, int w, int lane) {
    int len = g_ideg[w];
    if (len > ELLW) len = ELLW;
    const int* row = &g_ell[w * ELLW];
    __half2 h0 = t2[w * 32 + lane];                 // self
    __half2 h1 = __floats2half2_rn(0.f, 0.f);
    __half2 h2 = __floats2half2_rn(0.f, 0.f);
    __half2 h3 = __floats2half2_rn(0.f, 0.f);
    int m = len < 32 ? len : 32;
    int idx = (lane < m) ? row[lane] : 0;
    int k = 0;
    for (; k + 4 <= m; k += 4) {
        int s0 = __shfl_sync(0xffffffffu, idx, k);
        int s1 = __shfl_sync(0xffffffffu, idx, k + 1);
        int s2 = __shfl_sync(0xffffffffu, idx, k + 2);
        int s3 = __shfl_sync(0xffffffffu, idx, k + 3);
        h0 = __hadd2(h0, t2[s0 * 32 + lane]);
        h1 = __hadd2(h1, t2[s1 * 32 + lane]);
        h2 = __hadd2(h2, t2[s2 * 32 + lane]);
        h3 = __hadd2(h3, t2[s3 * 32 + lane]);
    }
    for (; k < m; k++) {
        int s0 = __shfl_sync(0xffffffffu, idx, k);
        h0 = __hadd2(h0, t2[s0 * 32 + lane]);
    }
    // rare tail: len > 32
    if (len > 32) {
        int mm = len - 32;
        int id2 = (lane < mm) ? row[32 + lane] : 0;
        for (int kk = 0; kk < mm; kk++) {
            int s0 = __shfl_sync(0xffffffffu, id2, kk);
            h0 = __hadd2(h0, t2[s0 * 32 + lane]);
        }
    }
    float2 r0 = __half22float2(h0);
    float2 r1 = __half22float2(h1);
    float2 r2 = __half22float2(h2);
    float2 r3 = __half22float2(h3);
    return make_float2((r0.x + r1.x) + (r2.x + r3.x),
                       (r0.y + r1.y) + (r2.y + r3.y));
}

__global__ void k_agg1(const float* __restrict__ b1, int n) {
    const __half2* t2 = reinterpret_cast<const __half2*>(g_th);
    int w = (blockIdx.x * blockDim.x + threadIdx.x) >> 5;
    int lane = threadIdx.x & 31;
    if (w >= n) return;
    float2 acc = agg_node(t2, w, lane);
    float dv = g_dinv[w];
    float2 bb = *reinterpret_cast<const float2*>(&b1[lane * 2]);
    float2 o;
    o.x = fmaxf(fmaf(dv, acc.x, bb.x), 0.0f);
    o.y = fmaxf(fmaf(dv, acc.y, bb.y), 0.0f);
    *reinterpret_cast<float2*>(&g_f[w * HH + lane * 2]) = o;
}

// t2' = dinv * (f1 @ W2); 16 nodes per 256-thread block
__global__ void k_xform2(const float* __restrict__ W2, int n) {
    __shared__ float sW[HH * HH];
    __shared__ float sRow[16][HH + 4];
    int tid = threadIdx.x;
    int nl = tid >> 4;
    int q  = tid & 15;
    int j4 = q * 4;
    int node = blockIdx.x * 16 + nl;

    for (int i = tid; i < HH * HH; i += 256) sW[i] = W2[i];
    if (node < n) {
        float4 r = *reinterpret_cast<const float4*>(&g_f[node * HH + j4]);
        sRow[nl][j4 + 0] = r.x; sRow[nl][j4 + 1] = r.y;
        sRow[nl][j4 + 2] = r.z; sRow[nl][j4 + 3] = r.w;
    }
    __syncthreads();

    if (node >= n) return;
    float a0 = 0.f, a1 = 0.f, a2 = 0.f, a3 = 0.f;
    #pragma unroll
    for (int k = 0; k < HH; k++) {
        float r = sRow[nl][k];
        float4 wv = *reinterpret_cast<const float4*>(&sW[k * HH + j4]);
        a0 = fmaf(r, wv.x, a0);
        a1 = fmaf(r, wv.y, a1);
        a2 = fmaf(r, wv.z, a2);
        a3 = fmaf(r, wv.w, a3);
    }
    float dv = g_dinv[node];
    __half2* out = reinterpret_cast<__half2*>(&g_th[node * HH + j4]);
    out[0] = __floats2half2_rn(dv * a0, dv * a1);
    out[1] = __floats2half2_rn(dv * a2, dv * a3);
}

// warp-per-node layer-2 agg fused with pooling
__global__ void k_agg2pool(const float* __restrict__ b2, const int* __restrict__ batch, int n) {
    const __half2* t2 = reinterpret_cast<const __half2*>(g_th);
    int w = (blockIdx.x * blockDim.x + threadIdx.x) >> 5;
    int lane = threadIdx.x & 31;
    if (w >= n) return;
    float2 acc = agg_node(t2, w, lane);
    float dv = g_dinv[w];
    float2 bb = *reinterpret_cast<const float2*>(&b2[lane * 2]);
    float vx = fmaxf(fmaf(dv, acc.x, bb.x), 0.0f);
    float vy = fmaxf(fmaf(dv, acc.y, bb.y), 0.0f);
    int b = batch[w];
    atomicAdd(&g_pool[b * HH + lane * 2 + 0], vx);
    atomicAdd(&g_pool[b * HH + lane * 2 + 1], vy);
}

// Head + restore zero-invariant for next call
__global__ void k_final(const float* __restrict__ Wf1, const float* __restrict__ bf1,
                        const float* __restrict__ Wf2, const float* __restrict__ bf2,
                        float* __restrict__ out) {
    __shared__ float sg[HH];
    __shared__ float sa[HH];
    int b = blockIdx.x;
    int j = threadIdx.x;

    float c = fmaxf(g_cnt[b], 1.0f);
    sg[j] = g_pool[b * HH + j] / c;
    __syncthreads();

    float acc = bf1[j];
    #pragma unroll
    for (int k = 0; k < HH; k++) acc += sg[k] * Wf1[k * HH + j];
    sa[j] = fmaxf(acc, 0.0f);
    __syncthreads();

    if (j < 4) {
        float o = bf2[j];
        #pragma unroll
        for (int k = 0; k < HH; k++) o += sa[k] * Wf2[k * 4 + j];
        out[b * 4 + j] = o;
    }

    // ---- restore zero-invariant ----
    g_pool[b * HH + j] = 0.0f;
    if (j == 0) g_cnt[b] = 0.0f;
    for (int i = b * HH + j; i < NN; i += GG * HH) g_ideg[i] = 0;
}

extern "C" void kernel_launch(void* const* d_in, const int* in_sizes, int n_in,
                              void* d_out, int out_size) {
    const float* x          = (const float*)d_in[0];
    const int*   edge_index = (const int*)d_in[1];
    const int*   batch      = (const int*)d_in[2];
    int wb = n_in - 8;
    const float* W1  = (const float*)d_in[wb + 0];
    const float* b1  = (const float*)d_in[wb + 1];
    const float* W2  = (const float*)d_in[wb + 2];
    const float* b2  = (const float*)d_in[wb + 3];
    const float* Wf1 = (const float*)d_in[wb + 4];
    const float* bf1 = (const float*)d_in[wb + 5];
    const float* Wf2 = (const float*)d_in[wb + 6];
    const float* bf2 = (const float*)d_in[wb + 7];

    int N = in_sizes[0] / 2;   // 100000
    int E = in_sizes[1] / 2;   // 1200000
    const int* src = edge_index;
    const int* dst = edge_index + E;

    float* out = (float*)d_out;
    (void)out_size;

    const int T = 256;
    int gN  = (N + T - 1) / T;
    int gE  = (E + T - 1) / T;
    int gNH = (N * HH + T - 1) / T;
    int gW  = (N * 32 + T - 1) / T;      // warp-per-node

    k_fill_ell<<<gE, T>>>(src, dst, E, batch, N);   // 0
    k_dinv<<<gN, T>>>(N);                           // 1
    k_xform1<<<gNH, T>>>(x, W1, N);                 // 2
    k_agg1<<<gW, T>>>(b1, N);                       // 3  <- profiled (verify HADD2 win)
    k_xform2<<<(N + 15) / 16, 256>>>(W2, N);        // 4
    k_agg2pool<<<gW, T>>>(b2, batch, N);            // 5
    k_final<<<GG, HH>>>(Wf1, bf1, Wf2, bf2, out);   // 6
}

// round 13
// speedup vs baseline: 1.3253x; 1.1631x over previous
#include <cuda_runtime.h>
#include <cuda_fp16.h>

#define NN 100000
#define HH 64
#define GG 512
#define ELLW 64           // fixed ELL width; P(deg>64) ~ 1e-30 for Poisson(12)
#define FULLM 0xffffffffu

// -------- scratch (device globals; zero-initialized at module load) --------
// INVARIANT: g_ideg, g_pool, g_cnt are all-zero on entry to every kernel_launch
// call. k_final restores this invariant at the end of each call.
__device__ int    g_ideg[NN];
__device__ int    g_ell[NN * ELLW];   // ELL: BYTE offsets (src*128) per dst node
__device__ float  g_dinv[NN];
__device__ __half g_th[NN * HH];      // pre-scaled transformed features (fp16, 128B/row)
__device__ float  g_f[NN * HH];       // layer-1 output (fp32)
__device__ float  g_pool[GG * HH];
__device__ float  g_cnt[GG];

__device__ __forceinline__ void red_add_v4(float* p, float4 v) {
    asm volatile(
        "{ .reg .u64 a; cvta.to.global.u64 a, %0;"
        "  red.global.add.v4.f32 [a], {%1, %2, %3, %4}; }"
        :: "l"(p), "f"(v.x), "f"(v.y), "f"(v.z), "f"(v.w)
        : "memory");
}

__device__ __forceinline__ __half2 u2h(unsigned u) {
    __half2 h; *reinterpret_cast<unsigned*>(&h) = u; return h;
}
__device__ __forceinline__ unsigned h2u(__half2 h) {
    return *reinterpret_cast<unsigned*>(&h);
}

// One pass: ELL fill (stores src*128 byte offsets) + warp-aggregated graph counts
__global__ void k_fill_ell(const int* __restrict__ src, const int* __restrict__ dst, int E,
                           const int* __restrict__ batch, int n) {
    int i = blockIdx.x * blockDim.x + threadIdx.x;
    if (i < E) {
        int d = dst[i];
        int slot = atomicAdd(&g_ideg[d], 1);
        if (slot < ELLW) g_ell[d * ELLW + slot] = src[i] << 7;   // byte offset into g_th
    }
    if (i < n) {
        int b = batch[i];
        unsigned active = __activemask();
        unsigned peers = __match_any_sync(active, b);
        int leader = __ffs(peers) - 1;
        int cnt = __popc(peers);
        if ((threadIdx.x & 31) == leader) atomicAdd(&g_cnt[b], (float)cnt);
    }
}

// t1' = dinv * (x @ W1), fp16 store; also writes g_dinv (j==0 lane per node)
__global__ void k_xform1(const float* __restrict__ x, const float* __restrict__ W1, int n) {
    int i = blockIdx.x * blockDim.x + threadIdx.x;
    if (i >= n * HH) return;
    int node = i >> 6;
    int j = i & 63;
    float dv = rsqrtf((float)g_ideg[node] + 1.0f);
    if (j == 0) g_dinv[node] = dv;
    float v = dv * (x[2 * node] * W1[j] + x[2 * node + 1] * W1[HH + j]);
    g_th[i] = __float2half(v);
}

// Half-warp-per-edge aggregation: 16 lanes cover one 128B feature row (uint2/lane).
// Warp processes 2 edges per step; fp16 accumulate; cross-half combine at end.
// Returns 4 features (sub*4 .. sub*4+3) as float4 — valid on lanes 0..15 only.
__device__ __forceinline__ float4 agg_node2(int w, int lane) {
    const char* base = (const char*)g_th;
    int len = g_ideg[w];
    if (len > ELLW) len = ELLW;
    const int* row = &g_ell[w * ELLW];
    int half = lane >> 4;          // 0 or 1: which edge of the pair
    int sub  = lane & 15;          // position within row
    int lb   = sub * 8;            // byte offset within a 128B row

    __half2 a0, a1;                // accumulator set A (self + even edges)
    __half2 b0 = u2h(0), b1 = u2h(0);   // accumulator set B (odd edges)
    if (half == 0) {               // self term only in half 0
        uint2 s = *reinterpret_cast<const uint2*>(base + w * 128 + lb);
        a0 = u2h(s.x); a1 = u2h(s.y);
    } else {
        a0 = u2h(0); a1 = u2h(0);
    }

    int m = len < 32 ? len : 32;
    int off = (lane < m) ? row[lane] : 0;   // coalesced index (byte-offset) load
    int k = 0;
    for (; k + 4 <= m; k += 4) {
        int o0 = __shfl_sync(FULLM, off, k + half);
        int o1 = __shfl_sync(FULLM, off, k + 2 + half);
        uint2 v0 = *reinterpret_cast<const uint2*>(base + o0 + lb);
        uint2 v1 = *reinterpret_cast<const uint2*>(base + o1 + lb);
        a0 = __hadd2(a0, u2h(v0.x)); a1 = __hadd2(a1, u2h(v0.y));
        b0 = __hadd2(b0, u2h(v1.x)); b1 = __hadd2(b1, u2h(v1.y));
    }
    for (; k + 2 <= m; k += 2) {
        int o0 = __shfl_sync(FULLM, off, k + half);
        uint2 v0 = *reinterpret_cast<const uint2*>(base + o0 + lb);
        a0 = __hadd2(a0, u2h(v0.x)); a1 = __hadd2(a1, u2h(v0.y));
    }
    if (k < m) {   // odd remainder: half 0 only
        int o0 = __shfl_sync(FULLM, off, k);
        if (half == 0) {
            uint2 v0 = *reinterpret_cast<const uint2*>(base + o0 + lb);
            a0 = __hadd2(a0, u2h(v0.x)); a1 = __hadd2(a1, u2h(v0.y));
        }
    }
    // rare tail: len > 32 (P ~ 1e-7 per node)
    for (int kk = 32; kk < len; kk++) {
        int o = row[kk];          // uniform load
        if (half == 0) {
            uint2 v = *reinterpret_cast<const uint2*>(base + o + lb);
            a0 = __hadd2(a0, u2h(v.x)); a1 = __hadd2(a1, u2h(v.y));
        }
    }

    a0 = __hadd2(a0, b0);
    a1 = __hadd2(a1, b1);
    // cross-half combine: lane s += lane s+16
    a0 = __hadd2(a0, u2h(__shfl_down_sync(FULLM, h2u(a0), 16)));
    a1 = __hadd2(a1, u2h(__shfl_down_sync(FULLM, h2u(a1), 16)));

    float2 f0 = __half22float2(a0);
    float2 f1 = __half22float2(a1);
    return make_float4(f0.x, f0.y, f1.x, f1.y);
}

__global__ void k_agg1(const float* __restrict__ b1, int n) {
    int w = (blockIdx.x * blockDim.x + threadIdx.x) >> 5;
    int lane = threadIdx.x & 31;
    if (w >= n) return;
    float4 acc = agg_node2(w, lane);
    if (lane < 16) {
        float dv = g_dinv[w];
        int sub = lane;
        float4 bb = *reinterpret_cast<const float4*>(&b1[sub * 4]);
        float4 o;
        o.x = fmaxf(fmaf(dv, acc.x, bb.x), 0.0f);
        o.y = fmaxf(fmaf(dv, acc.y, bb.y), 0.0f);
        o.z = fmaxf(fmaf(dv, acc.z, bb.z), 0.0f);
        o.w = fmaxf(fmaf(dv, acc.w, bb.w), 0.0f);
        *reinterpret_cast<float4*>(&g_f[w * HH + sub * 4]) = o;
    }
}

// t2' = dinv * (f1 @ W2); 16 nodes per 256-thread block
__global__ void k_xform2(const float* __restrict__ W2, int n) {
    __shared__ float sW[HH * HH];
    __shared__ float sRow[16][HH + 4];
    int tid = threadIdx.x;
    int nl = tid >> 4;
    int q  = tid & 15;
    int j4 = q * 4;
    int node = blockIdx.x * 16 + nl;

    for (int i = tid; i < HH * HH; i += 256) sW[i] = W2[i];
    if (node < n) {
        float4 r = *reinterpret_cast<const float4*>(&g_f[node * HH + j4]);
        sRow[nl][j4 + 0] = r.x; sRow[nl][j4 + 1] = r.y;
        sRow[nl][j4 + 2] = r.z; sRow[nl][j4 + 3] = r.w;
    }
    __syncthreads();

    if (node >= n) return;
    float a0 = 0.f, a1 = 0.f, a2 = 0.f, a3 = 0.f;
    #pragma unroll
    for (int k = 0; k < HH; k++) {
        float r = sRow[nl][k];
        float4 wv = *reinterpret_cast<const float4*>(&sW[k * HH + j4]);
        a0 = fmaf(r, wv.x, a0);
        a1 = fmaf(r, wv.y, a1);
        a2 = fmaf(r, wv.z, a2);
        a3 = fmaf(r, wv.w, a3);
    }
    float dv = g_dinv[node];
    __half2* out = reinterpret_cast<__half2*>(&g_th[node * HH + j4]);
    out[0] = __floats2half2_rn(dv * a0, dv * a1);
    out[1] = __floats2half2_rn(dv * a2, dv * a3);
}

// layer-2 agg fused with pooling: one RED.v4 per lane (lanes 0..15)
__global__ void k_agg2pool(const float* __restrict__ b2, const int* __restrict__ batch, int n) {
    int w = (blockIdx.x * blockDim.x + threadIdx.x) >> 5;
    int lane = threadIdx.x & 31;
    if (w >= n) return;
    float4 acc = agg_node2(w, lane);
    if (lane < 16) {
        float dv = g_dinv[w];
        int sub = lane;
        float4 bb = *reinterpret_cast<const float4*>(&b2[sub * 4]);
        float4 v;
        v.x = fmaxf(fmaf(dv, acc.x, bb.x), 0.0f);
        v.y = fmaxf(fmaf(dv, acc.y, bb.y), 0.0f);
        v.z = fmaxf(fmaf(dv, acc.z, bb.z), 0.0f);
        v.w = fmaxf(fmaf(dv, acc.w, bb.w), 0.0f);
        int b = batch[w];
        red_add_v4(&g_pool[b * HH + sub * 4], v);
    }
}

// Head + restore zero-invariant for next call
__global__ void k_final(const float* __restrict__ Wf1, const float* __restrict__ bf1,
                        const float* __restrict__ Wf2, const float* __restrict__ bf2,
                        float* __restrict__ out) {
    __shared__ float sg[HH];
    __shared__ float sa[HH];
    int b = blockIdx.x;
    int j = threadIdx.x;

    float c = fmaxf(g_cnt[b], 1.0f);
    sg[j] = g_pool[b * HH + j] / c;
    __syncthreads();

    float acc = bf1[j];
    #pragma unroll
    for (int k = 0; k < HH; k++) acc += sg[k] * Wf1[k * HH + j];
    sa[j] = fmaxf(acc, 0.0f);
    __syncthreads();

    if (j < 4) {
        float o = bf2[j];
        #pragma unroll
        for (int k = 0; k < HH; k++) o += sa[k] * Wf2[k * 4 + j];
        out[b * 4 + j] = o;
    }

    // ---- restore zero-invariant ----
    g_pool[b * HH + j] = 0.0f;
    if (j == 0) g_cnt[b] = 0.0f;
    for (int i = b * HH + j; i < NN; i += GG * HH) g_ideg[i] = 0;
}

extern "C" void kernel_launch(void* const* d_in, const int* in_sizes, int n_in,
                              void* d_out, int out_size) {
    const float* x          = (const float*)d_in[0];
    const int*   edge_index = (const int*)d_in[1];
    const int*   batch      = (const int*)d_in[2];
    int wb = n_in - 8;
    const float* W1  = (const float*)d_in[wb + 0];
    const float* b1  = (const float*)d_in[wb + 1];
    const float* W2  = (const float*)d_in[wb + 2];
    const float* b2  = (const float*)d_in[wb + 3];
    const float* Wf1 = (const float*)d_in[wb + 4];
    const float* bf1 = (const float*)d_in[wb + 5];
    const float* Wf2 = (const float*)d_in[wb + 6];
    const float* bf2 = (const float*)d_in[wb + 7];

    int N = in_sizes[0] / 2;   // 100000
    int E = in_sizes[1] / 2;   // 1200000
    const int* src = edge_index;
    const int* dst = edge_index + E;

    float* out = (float*)d_out;
    (void)out_size;

    const int T = 256;
    int gE  = (E + T - 1) / T;
    int gNH = (N * HH + T - 1) / T;
    int gW  = (N * 32 + T - 1) / T;      // warp-per-node

    k_fill_ell<<<gE, T>>>(src, dst, E, batch, N);   // 0
    k_xform1<<<gNH, T>>>(x, W1, N);                 // 1 (also writes dinv)
    k_agg1<<<gW, T>>>(b1, N);                       // 2
    k_xform2<<<(N + 15) / 16, 256>>>(W2, N);        // 3  <- profiled
    k_agg2pool<<<gW, T>>>(b2, batch, N);            // 4
    k_final<<<GG, HH>>>(Wf1, bf1, Wf2, bf2, out);   // 5
}

// round 14
// speedup vs baseline: 1.9448x; 1.4675x over previous
#include <cuda_runtime.h>
#include <cuda_fp16.h>

#define NN 100000
#define HH 64
#define GG 512
#define ELLW 64           // fixed ELL width; P(deg>64) ~ 1e-30 for Poisson(12)
#define FULLM 0xffffffffu

// -------- scratch (device globals; zero-initialized at module load) --------
// INVARIANT: g_ideg, g_pool, g_cnt are all-zero on entry to every kernel_launch
// call. k_final restores this invariant at the end of each call.
__device__ int    g_ideg[NN];
__device__ int    g_ell[NN * ELLW];   // ELL: BYTE offsets (src*128) per dst node
__device__ float  g_dinv[NN];
__device__ __half g_th[NN * HH];      // pre-scaled transformed features (fp16, 128B/row)
__device__ __half g_fh[NN * HH];      // layer-1 output (fp16, 128B/row)
__device__ float  g_pool[GG * HH];
__device__ float  g_cnt[GG];

__device__ __forceinline__ void red_add_v4(float* p, float4 v) {
    asm volatile(
        "{ .reg .u64 a; cvta.to.global.u64 a, %0;"
        "  red.global.add.v4.f32 [a], {%1, %2, %3, %4}; }"
        :: "l"(p), "f"(v.x), "f"(v.y), "f"(v.z), "f"(v.w)
        : "memory");
}

__device__ __forceinline__ __half2 u2h(unsigned u) {
    __half2 h; *reinterpret_cast<unsigned*>(&h) = u; return h;
}
__device__ __forceinline__ unsigned h2u(__half2 h) {
    return *reinterpret_cast<unsigned*>(&h);
}

// One pass: ELL fill (stores src*128 byte offsets) + warp-aggregated graph counts
__global__ void k_fill_ell(const int* __restrict__ src, const int* __restrict__ dst, int E,
                           const int* __restrict__ batch, int n) {
    int i = blockIdx.x * blockDim.x + threadIdx.x;
    if (i < E) {
        int d = dst[i];
        int slot = atomicAdd(&g_ideg[d], 1);
        if (slot < ELLW) g_ell[d * ELLW + slot] = src[i] << 7;   // byte offset into g_th
    }
    if (i < n) {
        int b = batch[i];
        unsigned active = __activemask();
        unsigned peers = __match_any_sync(active, b);
        int leader = __ffs(peers) - 1;
        int cnt = __popc(peers);
        if ((threadIdx.x & 31) == leader) atomicAdd(&g_cnt[b], (float)cnt);
    }
}

// t1' = dinv * (x @ W1), fp16 store; also writes g_dinv (j==0 lane per node)
__global__ void k_xform1(const float* __restrict__ x, const float* __restrict__ W1, int n) {
    int i = blockIdx.x * blockDim.x + threadIdx.x;
    if (i >= n * HH) return;
    int node = i >> 6;
    int j = i & 63;
    float dv = rsqrtf((float)g_ideg[node] + 1.0f);
    if (j == 0) g_dinv[node] = dv;
    float v = dv * (x[2 * node] * W1[j] + x[2 * node + 1] * W1[HH + j]);
    g_th[i] = __float2half(v);
}

// Half-warp-per-edge aggregation: 16 lanes cover one 128B feature row (uint2/lane).
// Warp processes 2 edges per step; fp16 accumulate; cross-half combine at end.
// Returns 4 features (sub*4 .. sub*4+3) as float4 — valid on lanes 0..15 only.
__device__ __forceinline__ float4 agg_node2(int w, int lane) {
    const char* base = (const char*)g_th;
    int len = g_ideg[w];
    if (len > ELLW) len = ELLW;
    const int* row = &g_ell[w * ELLW];
    int half = lane >> 4;
    int sub  = lane & 15;
    int lb   = sub * 8;

    __half2 a0, a1;
    __half2 b0 = u2h(0), b1 = u2h(0);
    if (half == 0) {
        uint2 s = *reinterpret_cast<const uint2*>(base + w * 128 + lb);
        a0 = u2h(s.x); a1 = u2h(s.y);
    } else {
        a0 = u2h(0); a1 = u2h(0);
    }

    int m = len < 32 ? len : 32;
    int off = (lane < m) ? row[lane] : 0;
    int k = 0;
    for (; k + 4 <= m; k += 4) {
        int o0 = __shfl_sync(FULLM, off, k + half);
        int o1 = __shfl_sync(FULLM, off, k + 2 + half);
        uint2 v0 = *reinterpret_cast<const uint2*>(base + o0 + lb);
        uint2 v1 = *reinterpret_cast<const uint2*>(base + o1 + lb);
        a0 = __hadd2(a0, u2h(v0.x)); a1 = __hadd2(a1, u2h(v0.y));
        b0 = __hadd2(b0, u2h(v1.x)); b1 = __hadd2(b1, u2h(v1.y));
    }
    for (; k + 2 <= m; k += 2) {
        int o0 = __shfl_sync(FULLM, off, k + half);
        uint2 v0 = *reinterpret_cast<const uint2*>(base + o0 + lb);
        a0 = __hadd2(a0, u2h(v0.x)); a1 = __hadd2(a1, u2h(v0.y));
    }
    if (k < m) {
        int o0 = __shfl_sync(FULLM, off, k);
        if (half == 0) {
            uint2 v0 = *reinterpret_cast<const uint2*>(base + o0 + lb);
            a0 = __hadd2(a0, u2h(v0.x)); a1 = __hadd2(a1, u2h(v0.y));
        }
    }
    for (int kk = 32; kk < len; kk++) {
        int o = row[kk];
        if (half == 0) {
            uint2 v = *reinterpret_cast<const uint2*>(base + o + lb);
            a0 = __hadd2(a0, u2h(v.x)); a1 = __hadd2(a1, u2h(v.y));
        }
    }

    a0 = __hadd2(a0, b0);
    a1 = __hadd2(a1, b1);
    a0 = __hadd2(a0, u2h(__shfl_down_sync(FULLM, h2u(a0), 16)));
    a1 = __hadd2(a1, u2h(__shfl_down_sync(FULLM, h2u(a1), 16)));

    float2 f0 = __half22float2(a0);
    float2 f1 = __half22float2(a1);
    return make_float4(f0.x, f0.y, f1.x, f1.y);
}

__global__ void k_agg1(const float* __restrict__ b1, int n) {
    int w = (blockIdx.x * blockDim.x + threadIdx.x) >> 5;
    int lane = threadIdx.x & 31;
    if (w >= n) return;
    float4 acc = agg_node2(w, lane);
    if (lane < 16) {
        float dv = g_dinv[w];
        int sub = lane;
        float4 bb = *reinterpret_cast<const float4*>(&b1[sub * 4]);
        float ox = fmaxf(fmaf(dv, acc.x, bb.x), 0.0f);
        float oy = fmaxf(fmaf(dv, acc.y, bb.y), 0.0f);
        float oz = fmaxf(fmaf(dv, acc.z, bb.z), 0.0f);
        float ow = fmaxf(fmaf(dv, acc.w, bb.w), 0.0f);
        uint2 u;
        u.x = h2u(__floats2half2_rn(ox, oy));
        u.y = h2u(__floats2half2_rn(oz, ow));
        *reinterpret_cast<uint2*>(&g_fh[w * HH + sub * 4]) = u;   // fp16 f1
    }
}

// t2' = dinv * (f1 @ W2) via tensor cores (mma.sync m16n8k16).
// Each warp: 16-node tiles, grid-stride; W2 fragments resident in registers.
__global__ void __launch_bounds__(128) k_xform2(const float* __restrict__ W2, int n) {
    int wid = (blockIdx.x * blockDim.x + threadIdx.x) >> 5;
    int lane = threadIdx.x & 31;
    int nwarps = gridDim.x * (blockDim.x >> 5);
    int l4 = lane >> 2;        // 0..7
    int lm = lane & 3;         // 0..3

    // B fragments: bf[kstep][ntile][2]; B is W2 (k x n), "col-major" fragment layout:
    // b0=W2[k0][nc], b1=W2[k0+1][nc], b2=W2[k0+8][nc], b3=W2[k0+9][nc]
    unsigned bf[4][8][2];
    #pragma unroll
    for (int s = 0; s < 4; s++) {
        int k0 = s * 16 + lm * 2;
        #pragma unroll
        for (int t = 0; t < 8; t++) {
            int nc = t * 8 + l4;
            bf[s][t][0] = h2u(__floats2half2_rn(W2[k0 * HH + nc], W2[(k0 + 1) * HH + nc]));
            bf[s][t][1] = h2u(__floats2half2_rn(W2[(k0 + 8) * HH + nc], W2[(k0 + 9) * HH + nc]));
        }
    }

    int ntiles = (n + 15) >> 4;
    for (int tile = wid; tile < ntiles; tile += nwarps) {
        int base = tile * 16;
        int r0 = base + l4;
        int r1 = r0 + 8;
        int r0c = r0 < n ? r0 : n - 1;
        int r1c = r1 < n ? r1 : n - 1;

        float c[8][4];
        #pragma unroll
        for (int t = 0; t < 8; t++) { c[t][0] = c[t][1] = c[t][2] = c[t][3] = 0.f; }

        #pragma unroll
        for (int s = 0; s < 4; s++) {
            int c0 = s * 16 + lm * 2;
            const unsigned* p0 = reinterpret_cast<const unsigned*>(&g_fh[r0c * HH + c0]);
            const unsigned* p1 = reinterpret_cast<const unsigned*>(&g_fh[r1c * HH + c0]);
            unsigned a0 = p0[0];       // A[r0][c0:c0+1]
            unsigned a1 = p1[0];       // A[r1][c0:c0+1]
            unsigned a2 = p0[4];       // A[r0][c0+8:c0+9]
            unsigned a3 = p1[4];       // A[r1][c0+8:c0+9]
            #pragma unroll
            for (int t = 0; t < 8; t++) {
                asm volatile(
                    "mma.sync.aligned.m16n8k16.row.col.f32.f16.f16.f32 "
                    "{%0,%1,%2,%3}, {%4,%5,%6,%7}, {%8,%9}, {%0,%1,%2,%3};"
                    : "+f"(c[t][0]), "+f"(c[t][1]), "+f"(c[t][2]), "+f"(c[t][3])
                    : "r"(a0), "r"(a1), "r"(a2), "r"(a3),
                      "r"(bf[s][t][0]), "r"(bf[s][t][1]));
            }
        }

        float dv0 = g_dinv[r0c];
        float dv1 = g_dinv[r1c];
        #pragma unroll
        for (int t = 0; t < 8; t++) {
            int col = t * 8 + lm * 2;
            if (r0 < n)
                *reinterpret_cast<unsigned*>(&g_th[r0 * HH + col]) =
                    h2u(__floats2half2_rn(dv0 * c[t][0], dv0 * c[t][1]));
            if (r1 < n)
                *reinterpret_cast<unsigned*>(&g_th[r1 * HH + col]) =
                    h2u(__floats2half2_rn(dv1 * c[t][2], dv1 * c[t][3]));
        }
    }
}

// layer-2 agg fused with pooling: one RED.v4 per lane (lanes 0..15)
__global__ void k_agg2pool(const float* __restrict__ b2, const int* __restrict__ batch, int n) {
    int w = (blockIdx.x * blockDim.x + threadIdx.x) >> 5;
    int lane = threadIdx.x & 31;
    if (w >= n) return;
    float4 acc = agg_node2(w, lane);
    if (lane < 16) {
        float dv = g_dinv[w];
        int sub = lane;
        float4 bb = *reinterpret_cast<const float4*>(&b2[sub * 4]);
        float4 v;
        v.x = fmaxf(fmaf(dv, acc.x, bb.x), 0.0f);
        v.y = fmaxf(fmaf(dv, acc.y, bb.y), 0.0f);
        v.z = fmaxf(fmaf(dv, acc.z, bb.z), 0.0f);
        v.w = fmaxf(fmaf(dv, acc.w, bb.w), 0.0f);
        int b = batch[w];
        red_add_v4(&g_pool[b * HH + sub * 4], v);
    }
}

// Head + restore zero-invariant for next call
__global__ void k_final(const float* __restrict__ Wf1, const float* __restrict__ bf1,
                        const float* __restrict__ Wf2, const float* __restrict__ bf2,
                        float* __restrict__ out) {
    __shared__ float sg[HH];
    __shared__ float sa[HH];
    int b = blockIdx.x;
    int j = threadIdx.x;

    float c = fmaxf(g_cnt[b], 1.0f);
    sg[j] = g_pool[b * HH + j] / c;
    __syncthreads();

    float acc = bf1[j];
    #pragma unroll
    for (int k = 0; k < HH; k++) acc += sg[k] * Wf1[k * HH + j];
    sa[j] = fmaxf(acc, 0.0f);
    __syncthreads();

    if (j < 4) {
        float o = bf2[j];
        #pragma unroll
        for (int k = 0; k < HH; k++) o += sa[k] * Wf2[k * 4 + j];
        out[b * 4 + j] = o;
    }

    // ---- restore zero-invariant ----
    g_pool[b * HH + j] = 0.0f;
    if (j == 0) g_cnt[b] = 0.0f;
    for (int i = b * HH + j; i < NN; i += GG * HH) g_ideg[i] = 0;
}

extern "C" void kernel_launch(void* const* d_in, const int* in_sizes, int n_in,
                              void* d_out, int out_size) {
    const float* x          = (const float*)d_in[0];
    const int*   edge_index = (const int*)d_in[1];
    const int*   batch      = (const int*)d_in[2];
    int wb = n_in - 8;
    const float* W1  = (const float*)d_in[wb + 0];
    const float* b1  = (const float*)d_in[wb + 1];
    const float* W2  = (const float*)d_in[wb + 2];
    const float* b2  = (const float*)d_in[wb + 3];
    const float* Wf1 = (const float*)d_in[wb + 4];
    const float* bf1 = (const float*)d_in[wb + 5];
    const float* Wf2 = (const float*)d_in[wb + 6];
    const float* bf2 = (const float*)d_in[wb + 7];

    int N = in_sizes[0] / 2;   // 100000
    int E = in_sizes[1] / 2;   // 1200000
    const int* src = edge_index;
    const int* dst = edge_index + E;

    float* out = (float*)d_out;
    (void)out_size;

    const int T = 256;
    int gE  = (E + T - 1) / T;
    int gNH = (N * HH + T - 1) / T;
    int gW  = (N * 32 + T - 1) / T;      // warp-per-node

    k_fill_ell<<<gE, T>>>(src, dst, E, batch, N);   // 0
    k_xform1<<<gNH, T>>>(x, W1, N);                 // 1 (also writes dinv)
    k_agg1<<<gW, T>>>(b1, N);                       // 2
    k_xform2<<<256, 128>>>(W2, N);                  // 3  <- profiled (verify mma)
    k_agg2pool<<<gW, T>>>(b2, batch, N);            // 4
    k_final<<<GG, HH>>>(Wf1, bf1, Wf2, bf2, out);   // 5
}